// round 10
// baseline (speedup 1.0000x reference)
#include <cuda_runtime.h>
#include <cstdint>

// SVConvTranspose2d, round 10: cp.async double-buffered weight staging
// (round 9 with the smem kw-stride bug fixed: 128 float4, not 64).
//
// x:      (4, 16, 128, 128) f32        -- 4 MB, L2-hot
// weight: (16, 16, 5, 5, 128, 128) f32 -- 419 MB DRAM-read exactly once,
//                                         streamed GMEM->SMEM via cp.async.cg
// bias:   (1, 16, 1, 1) f32
// out:    (4, 16, 128, 128) f32
//
// out[n,o,oh,ow] = bias[o] + sum wt[i,o,kh,kw,h,w] * x[n,i,h,w],
//   h = oh+2-kh (gather), ow = w+kw-2 (scatter into acc window).
//
// Pipeline: iteration = one (kh,ii). Stage tile = all weight quads the block
// needs for that iteration: [kw:5][(o2,ih):4][q:32] float4 = 10 KB.
// While stage k is consumed (LDS + FMA), stage k+1 is in flight via
// cp.async -- weight loads stay outstanding continuously, no weight regs.
//
// Block = 256 thr = (ih:2 i-slices of 8) x (np:2 batch-pairs) x (o2:2 outs)
//                   x (q:32 quads). np twins read the same smem weights.
// Grid  = 128 rows x 8 o-pairs = 1024 blocks.
// __launch_bounds__(256,5): 48-reg cap -> 40 warps/SM.
// Smem: 2x10 KB stages + 8 KB reduce = 28 KB.

#define H_  128
#define W_  128
#define HW  16384

__device__ __forceinline__ void cp_async16(uint32_t saddr, const void* gptr) {
    asm volatile("cp.async.cg.shared.global [%0], [%1], 16;\n"
                 :: "r"(saddr), "l"(gptr) : "memory");
}
__device__ __forceinline__ void cp_commit() {
    asm volatile("cp.async.commit_group;\n" ::: "memory");
}
__device__ __forceinline__ void cp_wait1() {
    asm volatile("cp.async.wait_group 1;\n" ::: "memory");
}

__global__ __launch_bounds__(256, 5)
void svct_kernel(const float* __restrict__ x,
                 const float* __restrict__ wt,
                 const float* __restrict__ bias,
                 float* __restrict__ out)
{
    __shared__ float4 stage[2][640];        // [buf][kw*128 + (o2*2+ih)*32 + q]
    __shared__ float  red[2][2][2][2][W_];  // [o2][np][m][ih][w]  8 KB

    const int t   = threadIdx.x;
    const int q   = t & 31;              // quad index in row == lane
    const int o2  = (t >> 5) & 1;        // which of the 2 outs
    const int np  = (t >> 6) & 1;        // batch pair: n in {2np, 2np+1}
    const int ih  = (t >> 7) & 1;        // i-slice of 8
    const int oh  = blockIdx.x >> 3;     // output row
    const int og  = blockIdx.x & 7;      // o-pair
    const int oc  = og * 2 + o2;         // output channel
    const int n0  = np * 2;
    const int ibase = ih * 8;

    // valid kh range so every address is in-bounds
    const int kh_lo = (oh > 125) ? (oh - 125) : 0;
    const int kh_hi = (oh < 2) ? (oh + 2) : 4;
    const int nit   = (kh_hi - kh_lo + 1) * 8;   // 24..40 iterations

    const bool issuer = (np == 0);
    // smem byte address of this thread's kw=0 stage slot
    const uint32_t sbase =
        (uint32_t)__cvta_generic_to_shared(&stage[0][(o2 * 2 + ih) * 32 + q]);
    const uint32_t sbuf_stride = 640 * 16;   // bytes per buffer
    const uint32_t skw_stride  = 128 * 16;   // bytes per kw slot (128 float4)

    float acc[2][8];
    #pragma unroll
    for (int m = 0; m < 2; m++)
        #pragma unroll
        for (int k = 0; k < 8; k++)
            acc[m][k] = 0.0f;

    // ---- prologue: issue stage 0
    if (issuer) {
        const int kh = kh_lo;
        const int i  = ibase;            // ii = 0
        const int h  = oh + 2 - kh;
        const float* wrow = wt + ((long)((i * 16 + oc) * 5 + kh) * 5) * HW
                               + (long)h * W_;
        #pragma unroll
        for (int kw = 0; kw < 5; kw++)
            cp_async16(sbase + kw * skw_stride,
                       (const float4*)(wrow + (long)kw * HW) + q);
    }
    cp_commit();

    #pragma unroll 1
    for (int itr = 0; itr < nit; itr++) {
        const int buf = itr & 1;

        // issue next stage into the other buffer
        const int nxt = itr + 1;
        if (issuer && nxt < nit) {
            const int kh2 = kh_lo + (nxt >> 3);
            const int i2  = ibase + (nxt & 7);
            const int h2  = oh + 2 - kh2;
            const float* wrow2 = wt + ((long)((i2 * 16 + oc) * 5 + kh2) * 5) * HW
                                    + (long)h2 * W_;
            const uint32_t sb2 = sbase + (nxt & 1) * sbuf_stride;
            #pragma unroll
            for (int kw = 0; kw < 5; kw++)
                cp_async16(sb2 + kw * skw_stride,
                           (const float4*)(wrow2 + (long)kw * HW) + q);
        }
        cp_commit();
        cp_wait1();                 // current stage complete, next in flight
        __syncthreads();

        // ---- consume current stage
        const int kh = kh_lo + (itr >> 3);
        const int i  = ibase + (itr & 7);
        const int h  = oh + 2 - kh;

        float4 xq[2];
        #pragma unroll
        for (int m = 0; m < 2; m++)
            xq[m] = __ldg((const float4*)x + (((n0 + m) * 16 + i) * H_ + h) * 32 + q);

        const float4* sl = &stage[buf][(o2 * 2 + ih) * 32 + q];
        #pragma unroll
        for (int kw = 0; kw < 5; kw++) {
            const float4 w4 = sl[kw * 128];
            const float wv[4] = {w4.x, w4.y, w4.z, w4.w};
            #pragma unroll
            for (int m = 0; m < 2; m++) {
                const float xv[4] = {xq[m].x, xq[m].y, xq[m].z, xq[m].w};
                #pragma unroll
                for (int j = 0; j < 4; j++)
                    acc[m][j + kw] = fmaf(wv[j], xv[j], acc[m][j + kw]);
            }
        }
        __syncthreads();            // protect buffer before it is re-issued
    }

    // cross-lane combine (4 shuffles per m), then smem-reduce the i-slices
    const bool q0  = (q == 0);
    const bool q31 = (q == 31);
    #pragma unroll
    for (int m = 0; m < 2; m++) {
        float up6 = __shfl_up_sync(0xffffffffu, acc[m][6], 1);
        float up7 = __shfl_up_sync(0xffffffffu, acc[m][7], 1);
        float dn0 = __shfl_down_sync(0xffffffffu, acc[m][0], 1);
        float dn1 = __shfl_down_sync(0xffffffffu, acc[m][1], 1);
        if (q0)  { up6 = 0.0f; up7 = 0.0f; }
        if (q31) { dn0 = 0.0f; dn1 = 0.0f; }
        *(float4*)&red[o2][np][m][ih][4 * q] =
            make_float4(acc[m][2] + up6, acc[m][3] + up7,
                        acc[m][4] + dn0, acc[m][5] + dn1);
    }
    __syncthreads();

    // 256 writer threads: (o2w:2) x (nw:4) x (qw:32)
    const int o2w = t >> 7;
    const int nw  = (t >> 5) & 3;
    const int qw  = t & 31;
    const int ocw = og * 2 + o2w;

    float4 s0 = *(const float4*)&red[o2w][nw >> 1][nw & 1][0][4 * qw];
    float4 s1 = *(const float4*)&red[o2w][nw >> 1][nw & 1][1][4 * qw];

    const float b = __ldg(bias + ocw);
    float4 r;
    r.x = s0.x + s1.x + b;
    r.y = s0.y + s1.y + b;
    r.z = s0.z + s1.z + b;
    r.w = s0.w + s1.w + b;

    ((float4*)out)[((nw * 16 + ocw) * H_ + oh) * 32 + qw] = r;
}

extern "C" void kernel_launch(void* const* d_in, const int* in_sizes, int n_in,
                              void* d_out, int out_size)
{
    const float* x    = (const float*)d_in[0];
    const float* wt   = (const float*)d_in[1];
    const float* bias = (const float*)d_in[2];
    float*       out  = (float*)d_out;

    svct_kernel<<<1024, 256>>>(x, wt, bias, out);
}

// round 11
// speedup vs baseline: 1.1602x; 1.1602x over previous
#include <cuda_runtime.h>
#include <cstdint>

// SVConvTranspose2d, round 11: 3-stage cp.async pipeline, ONE sync/iter.
//
// x:      (4, 16, 128, 128) f32        -- 4 MB, L2-hot
// weight: (16, 16, 5, 5, 128, 128) f32 -- 419 MB DRAM-read exactly once,
//                                         streamed GMEM->SMEM via cp.async.cg
// bias:   (1, 16, 1, 1) f32
// out:    (4, 16, 128, 128) f32
//
// out[n,o,oh,ow] = bias[o] + sum wt[i,o,kh,kw,h,w] * x[n,i,h,w],
//   h = oh+2-kh (gather), ow = w+kw-2 (scatter into acc window).
//
// Pipeline (S=3, canonical): prologue issues stages 0,1. Iteration itr:
//   wait_group 1   -> stage itr arrived, itr+1 still in flight
//   __syncthreads  -> publish stage itr; orders consume(itr-1) vs issue below
//   issue itr+2    -> 2 stages (20 KB/block) outstanding during consume
//   consume itr    -> 5 LDS.128 + 2 LDG.128(x) + 40 FMA per thread
// Buffer written at itr was consumed at itr-1; the sync at itr intervenes,
// so ONE barrier per iteration is sufficient.
//
// Stage tile: [kw:5][(o2,ih):4][q:32] float4 = 10 KB. Issue split over all
// 256 threads: np==0 -> kw{0,1,2}, np==1 -> kw{3,4}.
//
// Block = 256 thr = (ih:2 i-slices of 8) x (np:2 batch-pairs) x (o2:2 outs)
//                   x (q:32 quads). Grid = 128 rows x 8 o-pairs = 1024.
// __launch_bounds__(256,5): 48-reg cap -> 40 warps/SM; smem 38 KB (fits 5).

#define H_  128
#define W_  128
#define HW  16384

__device__ __forceinline__ void cp_async16(uint32_t saddr, const void* gptr) {
    asm volatile("cp.async.cg.shared.global [%0], [%1], 16;\n"
                 :: "r"(saddr), "l"(gptr) : "memory");
}
__device__ __forceinline__ void cp_commit() {
    asm volatile("cp.async.commit_group;\n" ::: "memory");
}
__device__ __forceinline__ void cp_wait1() {
    asm volatile("cp.async.wait_group 1;\n" ::: "memory");
}

__global__ __launch_bounds__(256, 5)
void svct_kernel(const float* __restrict__ x,
                 const float* __restrict__ wt,
                 const float* __restrict__ bias,
                 float* __restrict__ out)
{
    __shared__ float4 stage[3][640];        // [buf][kw*128 + (o2*2+ih)*32 + q] 30 KB
    __shared__ float  red[2][2][2][2][W_];  // [o2][np][m][ih][w]  8 KB

    const int t   = threadIdx.x;
    const int q   = t & 31;              // quad index in row == lane
    const int o2  = (t >> 5) & 1;        // which of the 2 outs
    const int np  = (t >> 6) & 1;        // batch pair: n in {2np, 2np+1}
    const int ih  = (t >> 7) & 1;        // i-slice of 8
    const int oh  = blockIdx.x >> 3;     // output row
    const int og  = blockIdx.x & 7;      // o-pair
    const int oc  = og * 2 + o2;         // output channel
    const int n0  = np * 2;
    const int ibase = ih * 8;

    // valid kh range so every address is in-bounds
    const int kh_lo = (oh > 125) ? (oh - 125) : 0;
    const int kh_hi = (oh < 2) ? (oh + 2) : 4;
    const int nit   = (kh_hi - kh_lo + 1) * 8;   // 24..40 iterations

    // issue split: np==0 -> kw 0..2, np==1 -> kw 3..4
    const int kw0 = np * 3;
    const int nkw = 3 - np;

    const uint32_t sbase =
        (uint32_t)__cvta_generic_to_shared(&stage[0][(o2 * 2 + ih) * 32 + q]);
    const uint32_t sbuf_stride = 640 * 16;   // bytes per buffer
    const uint32_t skw_stride  = 128 * 16;   // bytes per kw slot

    float acc[2][8];
    #pragma unroll
    for (int m = 0; m < 2; m++)
        #pragma unroll
        for (int k = 0; k < 8; k++)
            acc[m][k] = 0.0f;

    // stage issuer (stage s covers iteration s = (kh-kh_lo)*8 + ii)
    auto issue = [&](int s) {
        const int kh2 = kh_lo + (s >> 3);
        const int i2  = ibase + (s & 7);
        const int h2  = oh + 2 - kh2;
        const float* wrow2 = wt + ((long)((i2 * 16 + oc) * 5 + kh2) * 5) * HW
                                + (long)h2 * W_;
        const uint32_t sb = sbase + (uint32_t)(s % 3) * sbuf_stride;
        #pragma unroll
        for (int k = 0; k < 3; k++) {
            if (k < nkw) {
                const int kw = kw0 + k;
                cp_async16(sb + kw * skw_stride,
                           (const float4*)(wrow2 + (long)kw * HW) + q);
            }
        }
    };

    // ---- prologue: stages 0 and 1 (nit >= 24, so both exist)
    issue(0); cp_commit();
    issue(1); cp_commit();

    #pragma unroll 1
    for (int itr = 0; itr < nit; itr++) {
        cp_wait1();                 // stage itr arrived; itr+1 in flight
        __syncthreads();            // publish + order prev consume vs issue

        if (itr + 2 < nit) issue(itr + 2);
        cp_commit();

        // ---- consume stage itr
        const int kh = kh_lo + (itr >> 3);
        const int i  = ibase + (itr & 7);
        const int h  = oh + 2 - kh;

        float4 xq[2];
        #pragma unroll
        for (int m = 0; m < 2; m++)
            xq[m] = __ldg((const float4*)x + (((n0 + m) * 16 + i) * H_ + h) * 32 + q);

        const float4* sl = &stage[itr % 3][(o2 * 2 + ih) * 32 + q];
        #pragma unroll
        for (int kw = 0; kw < 5; kw++) {
            const float4 w4 = sl[kw * 128];
            const float wv[4] = {w4.x, w4.y, w4.z, w4.w};
            #pragma unroll
            for (int m = 0; m < 2; m++) {
                const float xv[4] = {xq[m].x, xq[m].y, xq[m].z, xq[m].w};
                #pragma unroll
                for (int j = 0; j < 4; j++)
                    acc[m][j + kw] = fmaf(wv[j], xv[j], acc[m][j + kw]);
            }
        }
    }

    // cross-lane combine (4 shuffles per m), then smem-reduce the i-slices
    __syncthreads();                // last consume done before red[] reuse
    const bool q0  = (q == 0);
    const bool q31 = (q == 31);
    #pragma unroll
    for (int m = 0; m < 2; m++) {
        float up6 = __shfl_up_sync(0xffffffffu, acc[m][6], 1);
        float up7 = __shfl_up_sync(0xffffffffu, acc[m][7], 1);
        float dn0 = __shfl_down_sync(0xffffffffu, acc[m][0], 1);
        float dn1 = __shfl_down_sync(0xffffffffu, acc[m][1], 1);
        if (q0)  { up6 = 0.0f; up7 = 0.0f; }
        if (q31) { dn0 = 0.0f; dn1 = 0.0f; }
        *(float4*)&red[o2][np][m][ih][4 * q] =
            make_float4(acc[m][2] + up6, acc[m][3] + up7,
                        acc[m][4] + dn0, acc[m][5] + dn1);
    }
    __syncthreads();

    // 256 writer threads: (o2w:2) x (nw:4) x (qw:32)
    const int o2w = t >> 7;
    const int nw  = (t >> 5) & 3;
    const int qw  = t & 31;
    const int ocw = og * 2 + o2w;

    float4 s0 = *(const float4*)&red[o2w][nw >> 1][nw & 1][0][4 * qw];
    float4 s1 = *(const float4*)&red[o2w][nw >> 1][nw & 1][1][4 * qw];

    const float b = __ldg(bias + ocw);
    float4 r;
    r.x = s0.x + s1.x + b;
    r.y = s0.y + s1.y + b;
    r.z = s0.z + s1.z + b;
    r.w = s0.w + s1.w + b;

    ((float4*)out)[((nw * 16 + ocw) * H_ + oh) * 32 + qw] = r;
}

extern "C" void kernel_launch(void* const* d_in, const int* in_sizes, int n_in,
                              void* d_out, int out_size)
{
    const float* x    = (const float*)d_in[0];
    const float* wt   = (const float*)d_in[1];
    const float* bias = (const float*)d_in[2];
    float*       out  = (float*)d_out;

    svct_kernel<<<1024, 256>>>(x, wt, bias, out);
}